// round 3
// baseline (speedup 1.0000x reference)
#include <cuda_runtime.h>
#include <math.h>

// Problem constants
#define CC    128
#define HWSZ  262144      // 512*512
#define BK    512         // B*K
#define NNEG  7
#define PP    4096
#define TAUI  (1.0f/0.07f)

// GEMM tiling
#define QT     32         // queries per block tile
#define PTILE  256        // protos per block
#define PCHUNK 128        // protos staged in smem at once
#define PSTR   132        // padded k-major stride for p tile
#define NPT    (PP/PTILE) // 16 proto tiles

// Scratch (device global — no allocation allowed)
__device__ float g_pmax[BK*NPT];   // per (query, ptile) max similarity

// ---- packed fp32x2 helpers (sm_100+) --------------------------------------
__device__ __forceinline__ void ffma2(unsigned long long& acc,
                                      unsigned long long a, unsigned long long b) {
    asm("fma.rn.f32x2 %0, %1, %2, %0;" : "+l"(acc) : "l"(a), "l"(b));
}
__device__ __forceinline__ unsigned long long dup2(float x) {
    unsigned long long r;
    asm("mov.b64 %0, {%1, %1};" : "=l"(r) : "f"(x));
    return r;
}
__device__ __forceinline__ float2 unpack2(unsigned long long v) {
    float2 r;
    asm("mov.b64 {%0, %1}, %2;" : "=f"(r.x), "=f"(r.y) : "l"(v));
    return r;
}

// ---------------------------------------------------------------------------
// Kernel 1: fully fused sim GEMM.  grid=(16,16), block=256
//   Each block: gathers + normalizes its own 32 queries straight from qf,
//   stages proto chunks (computing proto norms during staging), runs the
//   packed-f32x2 microtile GEMM, and emits per-(q, ptile) running max.
// ---------------------------------------------------------------------------
__global__ void k_gemm(const float* __restrict__ pool,
                       const float* __restrict__ qf,
                       const int*   __restrict__ qidx,
                       float* __restrict__ out) {
    extern __shared__ float sm[];
    float* q_t = sm;            // [128][QT]   k-major
    float* p_t = sm + CC * QT;  // [128][PSTR] k-major, padded
    __shared__ float psum[2 * PCHUNK];  // proto half sums of squares
    __shared__ float qpart[8 * QT];     // gather partial sums [seg][q]

    int t     = threadIdx.x;
    int qbase = blockIdx.x * QT;
    int pbase = blockIdx.y * PTILE;

    if (blockIdx.x == 0 && blockIdx.y == 0 && t == 0) out[0] = 0.0f;

    // ---- issue the query gather loads first (16 independent LDG, MLP=16) ----
    int gq = t & 31, seg = t >> 5;                 // q within tile, c-segment
    int gidx = qidx[qbase + gq];
    int gb   = (qbase + gq) >> 6;
    const float* gsrc = qf + ((size_t)(gb * CC + seg * 16)) * HWSZ + (size_t)gidx;
    float gv[16];
    #pragma unroll
    for (int i = 0; i < 16; i++) gv[i] = gsrc[(size_t)i * HWSZ];

    // ---- stage proto chunk 0 (transposed) + per-half sumsq ----
    int sp = t & 127, half = t >> 7;
    {
        const float* src = pool + (size_t)(pbase + sp) * CC + half * 64;
        float ssp = 0.0f;
        #pragma unroll
        for (int i = 0; i < 16; i++) {
            float4 v = *(const float4*)(src + i * 4);
            ssp += v.x * v.x + v.y * v.y + v.z * v.z + v.w * v.w;
            int k0 = half * 64 + i * 4;
            p_t[(k0 + 0) * PSTR + sp] = v.x;
            p_t[(k0 + 1) * PSTR + sp] = v.y;
            p_t[(k0 + 2) * PSTR + sp] = v.z;
            p_t[(k0 + 3) * PSTR + sp] = v.w;
        }
        psum[half * PCHUNK + sp] = ssp;
    }

    // ---- finish query gather: partial sumsq -> reduce -> normalized store ----
    {
        float ss = 0.0f;
        #pragma unroll
        for (int i = 0; i < 16; i++) ss += gv[i] * gv[i];
        qpart[seg * QT + gq] = ss;
    }
    __syncthreads();
    {
        float tot = 0.0f;
        #pragma unroll
        for (int s = 0; s < 8; s++) tot += qpart[s * QT + gq];
        float inv = 1.0f / fmaxf(sqrtf(tot), 1e-12f);
        #pragma unroll
        for (int i = 0; i < 16; i++)
            q_t[(seg * 16 + i) * QT + gq] = gv[i] * inv;   // lanes vary q: no conflicts
    }

    int qrow = t >> 6;   // 0..3  -> queries 8*qrow .. +7
    int pcol = t & 63;   // 0..63 -> protos  2*pcol, 2*pcol+1 (within chunk)

    float bv[8];
    #pragma unroll
    for (int i = 0; i < 8; i++) bv[i] = -3e38f;

    #pragma unroll
    for (int c = 0; c < PTILE / PCHUNK; c++) {
        if (c > 0) {
            __syncthreads();   // previous chunk fully consumed
            const float* src = pool + (size_t)(pbase + c * PCHUNK + sp) * CC + half * 64;
            float ssp = 0.0f;
            #pragma unroll
            for (int i = 0; i < 16; i++) {
                float4 v = *(const float4*)(src + i * 4);
                ssp += v.x * v.x + v.y * v.y + v.z * v.z + v.w * v.w;
                int k0 = half * 64 + i * 4;
                p_t[(k0 + 0) * PSTR + sp] = v.x;
                p_t[(k0 + 1) * PSTR + sp] = v.y;
                p_t[(k0 + 2) * PSTR + sp] = v.z;
                p_t[(k0 + 3) * PSTR + sp] = v.w;
            }
            psum[half * PCHUNK + sp] = ssp;
        }
        __syncthreads();

        unsigned long long acc[4][2];
        #pragma unroll
        for (int i = 0; i < 4; i++) { acc[i][0] = 0ull; acc[i][1] = 0ull; }

        const float* qp = q_t + 8 * qrow;
        const float* pp = p_t + 2 * pcol;
        #pragma unroll 8
        for (int k = 0; k < CC; k++) {
            ulonglong2 qa = *(const ulonglong2*)(qp + k * QT);      // (q0,q1),(q2,q3)
            ulonglong2 qb = *(const ulonglong2*)(qp + k * QT + 4);  // (q4,q5),(q6,q7)
            float2 pv = *(const float2*)(pp + k * PSTR);
            unsigned long long d0 = dup2(pv.x);
            unsigned long long d1 = dup2(pv.y);
            ffma2(acc[0][0], qa.x, d0); ffma2(acc[0][1], qa.x, d1);
            ffma2(acc[1][0], qa.y, d0); ffma2(acc[1][1], qa.y, d1);
            ffma2(acc[2][0], qb.x, d0); ffma2(acc[2][1], qb.x, d1);
            ffma2(acc[3][0], qb.y, d0); ffma2(acc[3][1], qb.y, d1);
        }

        // proto reciprocal norms from staged sums of squares
        float r0 = 1.0f / fmaxf(sqrtf(psum[2*pcol]   + psum[PCHUNK + 2*pcol]),   1e-12f);
        float r1 = 1.0f / fmaxf(sqrtf(psum[2*pcol+1] + psum[PCHUNK + 2*pcol+1]), 1e-12f);
        #pragma unroll
        for (int i = 0; i < 4; i++) {
            float2 a0 = unpack2(acc[i][0]);   // (q=8qrow+2i, p0), (q+1, p0)
            float2 a1 = unpack2(acc[i][1]);
            bv[2*i]   = fmaxf(bv[2*i],   fmaxf(a0.x * r0, a1.x * r1));
            bv[2*i+1] = fmaxf(bv[2*i+1], fmaxf(a0.y * r0, a1.y * r1));
        }
    }

    // max across the 32 lanes of each warp (warp shares qrow)
    #pragma unroll
    for (int o = 16; o; o >>= 1)
        #pragma unroll
        for (int i = 0; i < 8; i++)
            bv[i] = fmaxf(bv[i], __shfl_down_sync(0xffffffffu, bv[i], o));

    // combine the two warps sharing each qrow via smem, write g_pmax
    __syncthreads();
    int w = t >> 5;
    if ((t & 31) == 0) {
        #pragma unroll
        for (int i = 0; i < 8; i++) q_t[w * 8 + i] = bv[i];
    }
    __syncthreads();
    if (t < 32) {
        int r = t >> 3, qi = t & 7;
        float m = fmaxf(q_t[(2*r) * 8 + qi], q_t[(2*r+1) * 8 + qi]);
        g_pmax[(qbase + 8*r + qi) * NPT + blockIdx.y] = m;
    }
}

// ---------------------------------------------------------------------------
// Kernel 2: negatives + softmax CE + mean.  grid=64, block=256 (warp=query)
//   Re-derives the query vector from qf (L2-hot) — no g_qn round-trip.
// ---------------------------------------------------------------------------
__global__ void k_final(const float* __restrict__ neg,
                        const float* __restrict__ qf,
                        const int*   __restrict__ qidx,
                        float* __restrict__ out) {
    int q    = blockIdx.x * 8 + (threadIdx.x >> 5);
    int lane = threadIdx.x & 31;

    float v = (lane < NPT) ? g_pmax[q * NPT + lane] : -3e38f;
    #pragma unroll
    for (int o = 16; o; o >>= 1) v = fmaxf(v, __shfl_xor_sync(0xffffffffu, v, o));
    float l0 = v * TAUI;

    // gather this query's 4 channels (c = lane*4 .. +3), normalize in-warp
    int idx = qidx[q];
    int b   = q >> 6;
    const float* qp = qf + ((size_t)(b * CC + lane * 4)) * HWSZ + (size_t)idx;
    float qv[4];
    #pragma unroll
    for (int i = 0; i < 4; i++) qv[i] = qp[(size_t)i * HWSZ];
    float qss = qv[0]*qv[0] + qv[1]*qv[1] + qv[2]*qv[2] + qv[3]*qv[3];
    #pragma unroll
    for (int o = 16; o; o >>= 1) qss += __shfl_xor_sync(0xffffffffu, qss, o);
    float qinv = 1.0f / fmaxf(sqrtf(qss), 1e-12f);

    float ln[NNEG];
    #pragma unroll
    for (int n = 0; n < NNEG; n++) {
        float4 nv = *(const float4*)(neg + ((size_t)q * NNEG + n) * CC + lane * 4);
        float dp = qv[0] * nv.x + qv[1] * nv.y + qv[2] * nv.z + qv[3] * nv.w;
        float ss = nv.x * nv.x + nv.y * nv.y + nv.z * nv.z + nv.w * nv.w;
        #pragma unroll
        for (int o = 16; o; o >>= 1) {
            dp += __shfl_xor_sync(0xffffffffu, dp, o);
            ss += __shfl_xor_sync(0xffffffffu, ss, o);
        }
        ln[n] = dp * qinv / fmaxf(sqrtf(ss), 1e-12f) * TAUI;
    }

    if (lane == 0) {
        float m = l0;
        #pragma unroll
        for (int n = 0; n < NNEG; n++) m = fmaxf(m, ln[n]);
        float se = expf(l0 - m);
        #pragma unroll
        for (int n = 0; n < NNEG; n++) se += expf(ln[n] - m);
        float loss = logf(se) + m - l0;          // = -(log_softmax[0])
        atomicAdd(out, loss * (1.0f / (float)BK));
    }
}

// ---------------------------------------------------------------------------
extern "C" void kernel_launch(void* const* d_in, const int* in_sizes, int n_in,
                              void* d_out, int out_size) {
    const float* qf   = (const float*)d_in[0];  // [8,128,512,512]
    const float* pool = (const float*)d_in[1];  // [4096,128]
    const float* neg  = (const float*)d_in[2];  // [8,64,7,128]
    const int*   qidx = (const int*)d_in[3];    // [8,64]
    float* out = (float*)d_out;

    const int smem_gemm = (CC * QT + CC * PSTR) * (int)sizeof(float); // 83968 B
    cudaFuncSetAttribute(k_gemm, cudaFuncAttributeMaxDynamicSharedMemorySize, smem_gemm);

    k_gemm<<<dim3(BK / QT, PP / PTILE), 256, smem_gemm>>>(pool, qf, qidx, out);
    k_final<<<BK / 8, 256>>>(neg, qf, qidx, out);
}